// round 17
// baseline (speedup 1.0000x reference)
#include <cuda_runtime.h>
#include <cuda_fp16.h>
#include <cstdint>

#define TSEQ  512
#define BATCH 128
#define HID   1024
#define NLAY  4
#define BH    (BATCH*HID)
#define KTOT  2048              // K = concat(cur, hprev)
#define KC    128               // K per chunk (2 sub-tiles of 64 k-cols x 128 B)
#define NCH   (KTOT/KC)         // 16 chunks
#define SUBB  8192              // 64 rows x 128 B sub-tile
#define TILEB (2*SUBB)          // one operand (A or W) per chunk: 16 KB
#define STAGEB (2*TILEB)        // A + W = 32 KB / stage
#define STAGES 5
#define DYN_SMEM (STAGES*STAGEB + 256)   // 160 KB (reduction scratch reuses stage 0)

// ---------------- static device buffers ----------------
__device__ __align__(256) __half g_x16[(size_t)TSEQ*BH];              // x in fp16
__device__ __align__(256) __half g_r16[NLAY*2*BH];                    // hidden ring [layer][t&1]
__device__ __align__(256) __half g_w16[(size_t)NLAY*HID*KTOT];        // Wcat=[W_ih;W_hh], K-major

// ---------------- PTX helpers (baseline sm_80-level: safe on compute_103) -----
__device__ __forceinline__ unsigned smem_u32(const void* p) {
    unsigned a;
    asm("{ .reg .u64 t; cvta.to.shared.u64 t, %1; cvt.u32.u64 %0, t; }" : "=r"(a) : "l"(p));
    return a;
}
__device__ __forceinline__ void cp_async16(unsigned s, const void* g) {
    asm volatile("cp.async.cg.shared.global [%0], [%1], 16;\n" :: "r"(s), "l"(g));
}
__device__ __forceinline__ void cp_commit() { asm volatile("cp.async.commit_group;\n" ::: "memory"); }
template<int N>
__device__ __forceinline__ void cp_wait() { asm volatile("cp.async.wait_group %0;\n" :: "n"(N) : "memory"); }

__device__ __forceinline__ void ldsm4(unsigned& r0, unsigned& r1, unsigned& r2, unsigned& r3, unsigned a) {
    asm volatile("ldmatrix.sync.aligned.m8n8.x4.shared.b16 {%0,%1,%2,%3}, [%4];"
                 : "=r"(r0), "=r"(r1), "=r"(r2), "=r"(r3) : "r"(a));
}
__device__ __forceinline__ void mma16816(float4& c, const unsigned* a, unsigned b0, unsigned b1) {
    asm volatile("mma.sync.aligned.m16n8k16.row.col.f32.f16.f16.f32 "
                 "{%0,%1,%2,%3}, {%4,%5,%6,%7}, {%8,%9}, {%0,%1,%2,%3};"
                 : "+f"(c.x), "+f"(c.y), "+f"(c.z), "+f"(c.w)
                 : "r"(a[0]), "r"(a[1]), "r"(a[2]), "r"(a[3]), "r"(b0), "r"(b1));
}

// ---------------- conversion kernels (fp32 -> fp16) ----------------
__global__ void conv_x(const float* __restrict__ x) {
    size_t i = (size_t)blockIdx.x * blockDim.x + threadIdx.x;
    if (i >= (size_t)TSEQ * BH) return;
    g_x16[i] = __float2half(x[i]);
}
__global__ void conv_w(const float* __restrict__ Wih, const float* __restrict__ Whh) {
    size_t i = (size_t)blockIdx.x * blockDim.x + threadIdx.x;
    if (i >= (size_t)NLAY * HID * KTOT) return;
    int k = (int)(i & (KTOT - 1));
    size_t ln = i >> 11;                          // layer*HID + n
    float v = (k < HID) ? Wih[ln * HID + k] : Whh[ln * HID + (k - HID)];
    g_w16[i] = __float2half(v);
}

// ---------------- wavefront kernel ----------------
// 256 threads = 8 warps: group g = wid>>2 takes kk = g (mod 2) of each chunk;
// quadrant p = wid&3 is the 32x32 warp tile of the 64x64 CTA tile.
// 2 warps/SMSP hide dependency latency at CONSTANT bytes; partials reduced in smem.
__global__ void __launch_bounds__(256, 1)
rnn_wave_f16(int s, const float* __restrict__ bih, const float* __restrict__ bhh,
             float* __restrict__ out)
{
    const int layer = blockIdx.y;
    const int t = s - layer;
    if (t < 0 || t >= TSEQ) return;

    const int mt = blockIdx.x >> 4;        // 0..1
    const int nt = blockIdx.x & 15;        // 0..15
    const int m0 = mt * 64;
    const int n0 = nt * 64;

    extern __shared__ __align__(16) char dynsm[];
    const unsigned dbase = (smem_u32(dynsm) + 127) & ~127u;

    const int tid  = threadIdx.x;
    const int wid  = tid >> 5;
    const int lane = tid & 31;
    const int grp  = wid >> 2;             // 0..1: k16 residue class
    const int p    = wid & 3;              // quadrant
    const int wm   = p >> 1;               // warp M offset 32*wm
    const int wn   = p & 1;                // warp N offset 32*wn

    // ---- source pointers ----
    const __half* cur = (layer == 0) ? g_x16 + (size_t)t * BH
                                     : g_r16 + (size_t)((layer-1)*2 + (t & 1)) * BH;
    const __half* hprev = g_r16 + (size_t)(layer*2 + ((t-1) & 1)) * BH;
    const __half* w = g_w16 + (size_t)layer * HID * KTOT;

    const int nChunks = (t == 0) ? (NCH / 2) : NCH;   // KC=128 divides HID: no straddle

    // ---- producer: 256 threads; per chunk 8 cp.async/thread ----
    const int prow = tid >> 3;             // 0..31
    const int pg   = tid & 7;
    const unsigned so0 = (unsigned)(prow*128 + ((pg ^ (prow & 7)) << 4));

    auto issue_chunk = [&](int c, int buf) {
        const unsigned sb = dbase + buf * STAGEB;
        const int k0 = c * KC;
        const __half* asrc; int koff;
        if (k0 < HID) { asrc = cur;   koff = k0; }
        else          { asrc = hprev; koff = k0 - HID; }
        #pragma unroll
        for (int sub = 0; sub < 2; sub++) {
            const unsigned sa = sb + sub * SUBB;            // A sub-tile
            const unsigned sw = sb + TILEB + sub * SUBB;    // W sub-tile
            const int ks = koff + sub * 64;
            const int kw = k0 + sub * 64;
            #pragma unroll
            for (int i = 0; i < 2; i++) {
                const int row = prow + 32*i;
                const unsigned so = so0 + 4096u*i;          // (row&7) invariant under +32
                cp_async16(sa + so, asrc + (size_t)(m0+row)*HID + ks + pg*8);
                cp_async16(sw + so, w    + (size_t)(n0+row)*KTOT + kw + pg*8);
            }
        }
        cp_commit();
    };

    // ---- ldmatrix lane addressing ----
    const int x7 = lane & 7;
    const int asel = lane >> 4;
    const unsigned aRowOff0 = (unsigned)((wm*32 +      (lane & 15)) * 128);
    const unsigned aRowOff1 = (unsigned)((wm*32 + 16 + (lane & 15)) * 128);
    const int brow_in = (lane & 7) + ((lane & 16) >> 1);
    const int bsel = (lane >> 3) & 1;
    const unsigned bRowOff0 = (unsigned)((wn*32 +      brow_in) * 128);
    const unsigned bRowOff1 = (unsigned)((wn*32 + 16 + brow_in) * 128);

    float4 acc[2][4];
    #pragma unroll
    for (int mi = 0; mi < 2; mi++)
        #pragma unroll
        for (int nf = 0; nf < 4; nf++) acc[mi][nf] = make_float4(0.f, 0.f, 0.f, 0.f);

    // group's 4 k16 steps per chunk, processed in 2 pairs (8 LDSM in flight per pair)
    auto compute_chunk = [&](int buf) {
        const unsigned sb = dbase + buf * STAGEB;
        #pragma unroll
        for (int kp = 0; kp < 2; kp++) {
            unsigned a[2][2][4], b[2][2][4];
            #pragma unroll
            for (int u = 0; u < 2; u++) {
                const int kk = grp + kp*4 + u*2;            // residue grp mod 2
                const unsigned ss = sb + (unsigned)(kk >> 2) * SUBB;
                const int ki = kk & 3;
                const unsigned axor = (unsigned)(((ki*2 + asel) ^ x7) << 4);
                const unsigned bxor = (unsigned)(((ki*2 + bsel) ^ x7) << 4);
                ldsm4(a[u][0][0], a[u][0][1], a[u][0][2], a[u][0][3], ss + aRowOff0 + axor);
                ldsm4(a[u][1][0], a[u][1][1], a[u][1][2], a[u][1][3], ss + aRowOff1 + axor);
                ldsm4(b[u][0][0], b[u][0][1], b[u][0][2], b[u][0][3], ss + TILEB + bRowOff0 + bxor);
                ldsm4(b[u][1][0], b[u][1][1], b[u][1][2], b[u][1][3], ss + TILEB + bRowOff1 + bxor);
            }
            #pragma unroll
            for (int u = 0; u < 2; u++)
                #pragma unroll
                for (int mi = 0; mi < 2; mi++)
                    #pragma unroll
                    for (int nf = 0; nf < 4; nf++)
                        mma16816(acc[mi][nf], a[u][mi],
                                 b[u][nf>>1][(nf&1)*2], b[u][nf>>1][(nf&1)*2+1]);
        }
    };

    // ---- 5-stage pipeline: 4-chunk lookahead, one barrier per chunk ----
    issue_chunk(0, 0);
    issue_chunk(1, 1);
    issue_chunk(2, 2);
    issue_chunk(3, 3);
    for (int c = 0; c < nChunks; c++) {
        if      (c + 3 < nChunks) cp_wait<3>();
        else if (c + 2 < nChunks) cp_wait<2>();
        else if (c + 1 < nChunks) cp_wait<1>();
        else                      cp_wait<0>();
        __syncthreads();          // chunk c visible; stage (c+4)%5 free (compute c-1 done)
        if (c + 4 < nChunks) issue_chunk(c + 4, (c + 4) % STAGES);
        compute_chunk(c % STAGES);
    }

    // ---- cross-group reduction (stage smem is dead now) ----
    __syncthreads();
    float4* red = (float4*)(dynsm + (dbase - smem_u32(dynsm)));
    if (grp == 1) {
        #pragma unroll
        for (int mi = 0; mi < 2; mi++)
            #pragma unroll
            for (int nf = 0; nf < 4; nf++)
                red[p*256 + (mi*4 + nf)*32 + lane] = acc[mi][nf];
    }
    __syncthreads();
    if (grp == 0) {
        #pragma unroll
        for (int mi = 0; mi < 2; mi++)
            #pragma unroll
            for (int nf = 0; nf < 4; nf++) {
                float4 v = red[p*256 + (mi*4 + nf)*32 + lane];
                acc[mi][nf].x += v.x; acc[mi][nf].y += v.y;
                acc[mi][nf].z += v.z; acc[mi][nf].w += v.w;
            }

        // ---- epilogue (group 0): bias + tanh, fp16 to ring, fp32 to out for top layer ----
        const size_t rb = (size_t)(layer*2 + (t & 1)) * BH;
        #pragma unroll
        for (int mi = 0; mi < 2; mi++) {
            const int mlo = m0 + wm*32 + mi*16 + (lane >> 2);
            #pragma unroll
            for (int nf = 0; nf < 4; nf++) {
                const int n = n0 + wn*32 + nf*8 + (lane & 3)*2;
                const float b0 = bih[layer*HID + n]     + bhh[layer*HID + n];
                const float b1 = bih[layer*HID + n + 1] + bhh[layer*HID + n + 1];
                const float v00 = tanhf(acc[mi][nf].x + b0);
                const float v01 = tanhf(acc[mi][nf].y + b1);
                const float v10 = tanhf(acc[mi][nf].z + b0);
                const float v11 = tanhf(acc[mi][nf].w + b1);
                #pragma unroll
                for (int rh = 0; rh < 2; rh++) {
                    const int m = mlo + rh*8;
                    const float va = rh ? v10 : v00;
                    const float vb = rh ? v11 : v01;
                    const __half ha = __float2half(va);
                    const __half hb = __float2half(vb);
                    const unsigned hpack = (unsigned)__half_as_ushort(ha) |
                                           ((unsigned)__half_as_ushort(hb) << 16);
                    *reinterpret_cast<unsigned*>(&g_r16[rb + (size_t)m*HID + n]) = hpack;
                    if (layer == NLAY - 1) {
                        float2 o = make_float2(va, vb);
                        *reinterpret_cast<float2*>(&out[(size_t)t*BH + (size_t)m*HID + n]) = o;
                    }
                }
            }
        }
    }
}

extern "C" void kernel_launch(void* const* d_in, const int* in_sizes, int n_in,
                              void* d_out, int out_size) {
    const float* x   = (const float*)d_in[0];
    const float* Wih = (const float*)d_in[1];
    const float* Whh = (const float*)d_in[2];
    const float* bih = (const float*)d_in[3];
    const float* bhh = (const float*)d_in[4];
    float* out = (float*)d_out;

    cudaFuncSetAttribute(rnn_wave_f16, cudaFuncAttributeMaxDynamicSharedMemorySize, DYN_SMEM);

    // One-time (per replay) fp32 -> fp16 conversion
    conv_x<<<(unsigned)(((size_t)TSEQ*BH + 255) / 256), 256>>>(x);
    conv_w<<<(unsigned)(((size_t)NLAY*HID*KTOT + 255) / 256), 256>>>(Wih, Whh);

    // Wavefront s = t + layer: 515 sequential launches; kernel boundaries = sync.
    const dim3 grid(32, NLAY);
    for (int s = 0; s < TSEQ + NLAY - 1; s++) {
        rnn_wave_f16<<<grid, 256, DYN_SMEM>>>(s, bih, bhh, out);
    }
}